// round 8
// baseline (speedup 1.0000x reference)
#include <cuda_runtime.h>

// Problem constants
#define NP    64     // B*NUM_PARTS = 16*4
#define PC    32     // channels per part
#define HH    64
#define WW    512
#define HB    4      // h rows per K4 CTA
#define WQ    128    // w quarter width per K4 CTA
#define NCP   16     // channel pairs

typedef unsigned long long u64;

__device__ __forceinline__ u64 pk2(float a, float b) {
    u64 r; asm("mov.b64 %0, {%1,%2};" : "=l"(r) : "f"(a), "f"(b)); return r;
}
__device__ __forceinline__ void upk2(u64 v, float& a, float& b) {
    asm("mov.b64 {%0,%1}, %2;" : "=f"(a), "=f"(b) : "l"(v));
}
__device__ __forceinline__ void ffma2(u64& d, u64 a, u64 b) {
    asm("fma.rn.f32x2 %0, %1, %2, %0;" : "+l"(d) : "l"(a), "l"(b));
}

// branchless sigmoid: 2 MUFU ops, no divergence, ~2^-21 accuracy
__device__ __forceinline__ float sigf(float t) {
    float e = __expf(-fabsf(t));
    float s = __fdividef(1.0f, 1.0f + e);   // sigmoid(|t|)
    return (t >= 0.0f) ? s : 1.0f - s;
}

// Scratch (device globals, allocation-free)
__device__ float g_havg[NP * PC * HH];
__device__ float g_hmax[NP * PC * HH];
__device__ float g_wavg[NP * PC * WW];
__device__ float g_wmax[NP * PC * WW];
__device__ float g_ph[NP * PC * HH];
__device__ float g_pw[NP * PC * WW];

// ---------------------------------------------------------------------------
// K1: per-(n,c) slice stats. Quad-level shfl reduce + smem partials.
// grid 2048, 256 threads
// ---------------------------------------------------------------------------
__global__ __launch_bounds__(256) void k1_stats(const float* __restrict__ x) {
    const int nc  = blockIdx.x;
    const int tid = threadIdx.x;
    const int r2  = tid >> 7;        // 0/1: which row of a 2-row stripe
    const int c4  = tid & 127;       // float4 column 0..127

    const float4* xs = reinterpret_cast<const float4*>(x + (size_t)nc * HH * WW);

    __shared__ float rs[HH][33], rm[HH][33];   // 33: kill final-reduce bank conflict
    __shared__ float csh[WW], cmh[WW];

    float cs0 = 0.f, cs1 = 0.f, cs2 = 0.f, cs3 = 0.f;
    float cm0 = -3.4e38f, cm1 = -3.4e38f, cm2 = -3.4e38f, cm3 = -3.4e38f;
    const int q = c4 >> 2;

    for (int h0 = 0; h0 < HH; h0 += 2) {
        const int h = h0 + r2;
        float4 v = xs[h * 128 + c4];
        cs0 += v.x; cs1 += v.y; cs2 += v.z; cs3 += v.w;
        cm0 = fmaxf(cm0, v.x); cm1 = fmaxf(cm1, v.y);
        cm2 = fmaxf(cm2, v.z); cm3 = fmaxf(cm3, v.w);
        float s = (v.x + v.y) + (v.z + v.w);
        float m = fmaxf(fmaxf(v.x, v.y), fmaxf(v.z, v.w));
        s += __shfl_xor_sync(0xffffffffu, s, 1);
        m  = fmaxf(m, __shfl_xor_sync(0xffffffffu, m, 1));
        s += __shfl_xor_sync(0xffffffffu, s, 2);
        m  = fmaxf(m, __shfl_xor_sync(0xffffffffu, m, 2));
        if ((tid & 3) == 0) { rs[h][q] = s; rm[h][q] = m; }
    }
    __syncthreads();

    if (tid < HH) {
        float s = 0.f, m = -3.4e38f;
        #pragma unroll
        for (int k = 0; k < 32; k++) { s += rs[tid][k]; m = fmaxf(m, rm[tid][k]); }
        g_havg[nc * HH + tid] = s * (1.0f / (float)WW);
        g_hmax[nc * HH + tid] = m;
    }

    if (r2 == 0) {
        csh[c4 * 4 + 0] = cs0; csh[c4 * 4 + 1] = cs1; csh[c4 * 4 + 2] = cs2; csh[c4 * 4 + 3] = cs3;
        cmh[c4 * 4 + 0] = cm0; cmh[c4 * 4 + 1] = cm1; cmh[c4 * 4 + 2] = cm2; cmh[c4 * 4 + 3] = cm3;
    }
    __syncthreads();
    if (r2 == 1) {
        const int w = c4 * 4;
        g_wavg[nc * WW + w + 0] = (cs0 + csh[w + 0]) * (1.0f / (float)HH);
        g_wavg[nc * WW + w + 1] = (cs1 + csh[w + 1]) * (1.0f / (float)HH);
        g_wavg[nc * WW + w + 2] = (cs2 + csh[w + 2]) * (1.0f / (float)HH);
        g_wavg[nc * WW + w + 3] = (cs3 + csh[w + 3]) * (1.0f / (float)HH);
        g_wmax[nc * WW + w + 0] = fmaxf(cm0, cmh[w + 0]);
        g_wmax[nc * WW + w + 1] = fmaxf(cm1, cmh[w + 1]);
        g_wmax[nc * WW + w + 2] = fmaxf(cm2, cmh[w + 2]);
        g_wmax[nc * WW + w + 3] = fmaxf(cm3, cmh[w + 3]);
    }
}

// ---------------------------------------------------------------------------
// K23: merged ph conv (blocks [0,64)) + pw conv (blocks [64,320), o split 4-way)
// 256 threads. dynamic smem: k3-part needs 34304 floats = 137216 B
// ---------------------------------------------------------------------------
__global__ __launch_bounds__(256) void k23(const float* __restrict__ w_h,
                                           const float* __restrict__ b_h,
                                           const float* __restrict__ w_w,
                                           const float* __restrict__ b_w) {
    extern __shared__ float sm[];
    const int bid = blockIdx.x;
    const int tid = threadIdx.x;

    if (bid < 64) {
        // ---------------- ph: conv 3x2 pad(h)=1 + relu + softmax over h ----
        const int n = bid;
        float* ha = sm;                 // [32][64]
        float* hm = sm + PC * HH;       // [32][64]
        float* wh = sm + 2 * PC * HH;   // 6144

        for (int idx = tid; idx < PC * HH; idx += 256) {
            ha[idx] = g_havg[n * PC * HH + idx];
            hm[idx] = g_hmax[n * PC * HH + idx];
        }
        for (int idx = tid; idx < PC * PC * 6; idx += 256) wh[idx] = w_h[idx];
        __syncthreads();

        const int o  = tid >> 3;     // 0..31
        const int j  = tid & 7;      // 8 threads per o, 8 h each
        const int hb = j * 8;

        float acc[8];
        const float bo = b_h[o];
        #pragma unroll
        for (int t = 0; t < 8; t++) acc[t] = bo;

        for (int i = 0; i < PC; i++) {
            const float* wp = &wh[(o * PC + i) * 6];
            const float w00 = wp[0], w01 = wp[1], w10 = wp[2], w11 = wp[3], w20 = wp[4], w21 = wp[5];
            const float* A = ha + i * HH;
            const float* M = hm + i * HH;
            float wA[10], wM[10];
            wA[0] = (hb > 0) ? A[hb - 1] : 0.f;
            wM[0] = (hb > 0) ? M[hb - 1] : 0.f;
            #pragma unroll
            for (int t = 0; t < 8; t++) { wA[t + 1] = A[hb + t]; wM[t + 1] = M[hb + t]; }
            wA[9] = (hb + 8 < HH) ? A[hb + 8] : 0.f;
            wM[9] = (hb + 8 < HH) ? M[hb + 8] : 0.f;
            #pragma unroll
            for (int t = 0; t < 8; t++) {
                acc[t] += wA[t] * w00 + wM[t] * w01
                        + wA[t + 1] * w10 + wM[t + 1] * w11
                        + wA[t + 2] * w20 + wM[t + 2] * w21;
            }
        }

        float lm = -3.4e38f;
        #pragma unroll
        for (int t = 0; t < 8; t++) { acc[t] = fmaxf(acc[t], 0.f); lm = fmaxf(lm, acc[t]); }
        #pragma unroll
        for (int off = 1; off <= 4; off <<= 1) lm = fmaxf(lm, __shfl_xor_sync(0xffffffffu, lm, off));
        float ls = 0.f;
        #pragma unroll
        for (int t = 0; t < 8; t++) { acc[t] = __expf(acc[t] - lm); ls += acc[t]; }
        #pragma unroll
        for (int off = 1; off <= 4; off <<= 1) ls += __shfl_xor_sync(0xffffffffu, ls, off);
        const float inv = 1.0f / ls;
        #pragma unroll
        for (int t = 0; t < 8; t++) g_ph[(n * PC + o) * HH + hb + t] = acc[t] * inv;
    } else {
        // ---------------- pw: conv 2x3 pad(w)=1 + relu + softmax over w ----
        const int b2 = bid - 64;
        const int n  = b2 >> 2;
        const int og = b2 & 3;          // o group of 8

        float* wa = sm;                  // [32][512]
        float* wm = sm + PC * WW;        // [32][512]
        float* ww = sm + 2 * PC * WW;    // 8*32*6 = 1536

        {
            const float4* sa = reinterpret_cast<const float4*>(g_wavg + n * PC * WW);
            const float4* sx = reinterpret_cast<const float4*>(g_wmax + n * PC * WW);
            float4* da = reinterpret_cast<float4*>(wa);
            float4* dm = reinterpret_cast<float4*>(wm);
            for (int idx = tid; idx < PC * WW / 4; idx += 256) { da[idx] = sa[idx]; dm[idx] = sx[idx]; }
        }
        {
            const float* src = w_w + og * 8 * PC * 6;
            for (int idx = tid; idx < 8 * PC * 6; idx += 256) ww[idx] = src[idx];
        }
        __syncthreads();

        const int oo = tid >> 5;            // 0..7 within group
        const int o  = og * 8 + oo;
        const int j  = tid & 31;            // one warp per o

        float acc[16];
        const float bo = b_w[o];
        #pragma unroll
        for (int t = 0; t < 16; t++) acc[t] = bo;

        for (int i = 0; i < PC; i++) {
            const float* wp = &ww[(oo * PC + i) * 6];
            const float a0 = wp[0], a1 = wp[1], a2 = wp[2];
            const float m0 = wp[3], m1 = wp[4], m2 = wp[5];
            const float* A = wa + i * WW;
            const float* M = wm + i * WW;
            #pragma unroll
            for (int k = 0; k < 4; k++) {
                const int w0 = j * 4 + k * 128;
                float4 av = *reinterpret_cast<const float4*>(&A[w0]);
                float4 mv = *reinterpret_cast<const float4*>(&M[w0]);
                float am1 = (w0 > 0) ? A[w0 - 1] : 0.f;
                float mm1 = (w0 > 0) ? M[w0 - 1] : 0.f;
                float ap4 = (w0 + 4 < WW) ? A[w0 + 4] : 0.f;
                float mp4 = (w0 + 4 < WW) ? M[w0 + 4] : 0.f;
                acc[k*4+0] += am1 * a0 + av.x * a1 + av.y * a2 + mm1 * m0 + mv.x * m1 + mv.y * m2;
                acc[k*4+1] += av.x * a0 + av.y * a1 + av.z * a2 + mv.x * m0 + mv.y * m1 + mv.z * m2;
                acc[k*4+2] += av.y * a0 + av.z * a1 + av.w * a2 + mv.y * m0 + mv.z * m1 + mv.w * m2;
                acc[k*4+3] += av.z * a0 + av.w * a1 + ap4 * a2 + mv.z * m0 + mv.w * m1 + mp4 * m2;
            }
        }

        float lm = -3.4e38f;
        #pragma unroll
        for (int t = 0; t < 16; t++) { acc[t] = fmaxf(acc[t], 0.f); lm = fmaxf(lm, acc[t]); }
        #pragma unroll
        for (int off = 1; off <= 16; off <<= 1) lm = fmaxf(lm, __shfl_xor_sync(0xffffffffu, lm, off));
        float ls = 0.f;
        #pragma unroll
        for (int t = 0; t < 16; t++) { acc[t] = __expf(acc[t] - lm); ls += acc[t]; }
        #pragma unroll
        for (int off = 1; off <= 16; off <<= 1) ls += __shfl_xor_sync(0xffffffffu, ls, off);
        const float inv = 1.0f / ls;

        float* dst = g_pw + (n * PC + o) * WW;
        #pragma unroll
        for (int k = 0; k < 4; k++) {
            const int w0 = j * 4 + k * 128;
            float4 r;
            r.x = acc[k*4+0] * inv; r.y = acc[k*4+1] * inv;
            r.z = acc[k*4+2] * inv; r.w = acc[k*4+3] * inv;
            *reinterpret_cast<float4*>(&dst[w0]) = r;
        }
    }
}

// ---------------------------------------------------------------------------
// K4: apply. One CTA per (n, h-block of 4, w-quarter). C-PAIRED FFMA2:
// pwi[cp][w] = (pw[2cp][w], pw[2cp+1][w]), Atp[hl][cp][o] = paired At values.
// acc.lo+acc.hi = sum over c -> ZERO MOVs in the mainloop.
// Per c-pair iter: 16 FFMA2 + 5 LDS. Coalesced LDG.64/STG.64 epilogue.
// dyn smem: pwi[16][128] u64 (16KB) + Atp[4][16][32] u64 (16KB) = 32KB, 3 CTAs/SM
// ---------------------------------------------------------------------------
__global__ __launch_bounds__(256, 3) void k4_apply(const float* __restrict__ x,
                                                   const float* __restrict__ w_e,
                                                   const float* __restrict__ b_e,
                                                   float* __restrict__ out) {
    extern __shared__ float sm4[];
    u64* pwi = reinterpret_cast<u64*>(sm4);            // [16][128]
    u64* Atp = reinterpret_cast<u64*>(sm4) + NCP * WQ; // [4][16][32]
    __shared__ float phs[HB * PC];

    const int bid = blockIdx.x;
    const int n   = bid >> 6;
    const int hb  = (bid >> 2) & 15;   // h = hb*4 + hl
    const int wq  = bid & 3;           // w quarter
    const int tid = threadIdx.x;

    // stage pw quarter tile, interleaved by channel pair
    {
        const float* pwg = g_pw + n * PC * WW + wq * WQ;
        for (int idx = tid; idx < NCP * WQ; idx += 256) {
            const int cp = idx >> 7, w = idx & 127;
            pwi[idx] = pk2(pwg[(2 * cp) * WW + w], pwg[(2 * cp + 1) * WW + w]);
        }
    }
    if (tid < HB * PC) {
        const int hl = tid >> 5, c = tid & 31;
        phs[tid] = g_ph[(n * PC + c) * HH + hb * HB + hl];
    }
    __syncthreads();

    // Atp[hl][cp][o] = (w_e[o][2cp]*ph[2cp], w_e[o][2cp+1]*ph[2cp+1])
    for (int idx = tid; idx < HB * NCP * PC; idx += 256) {
        const int hl = idx >> 9;
        const int cp = (idx >> 5) & 15;
        const int o  = idx & 31;
        Atp[idx] = pk2(w_e[o * PC + 2 * cp]     * phs[hl * PC + 2 * cp],
                       w_e[o * PC + 2 * cp + 1] * phs[hl * PC + 2 * cp + 1]);
    }
    __syncthreads();

    const int wid  = tid >> 5;            // 0..7
    const int lane = tid & 31;
    const int o0   = (wid & 3) * 8;       // 8 contiguous o per warp
    const int wofs = (wid >> 2) * 64 + lane * 2;   // contiguous w within quarter

    // hoist biases
    const float4 beL = *reinterpret_cast<const float4*>(&b_e[o0]);
    const float4 beH = *reinterpret_cast<const float4*>(&b_e[o0 + 4]);
    const float be_[8] = { beL.x, beL.y, beL.z, beL.w, beH.x, beH.y, beH.z, beH.w };

    #pragma unroll 1
    for (int hl = 0; hl < HB; hl++) {
        const int h = hb * HB + hl;
        const u64* At = Atp + hl * (NCP * PC);

        u64 acc[8][2];
        #pragma unroll
        for (int oi = 0; oi < 8; oi++) { acc[oi][0] = 0ull; acc[oi][1] = 0ull; }

        #pragma unroll 4
        for (int cp = 0; cp < NCP; cp++) {
            const ulonglong2* ap = reinterpret_cast<const ulonglong2*>(&At[cp * PC + o0]);
            const ulonglong2 p0 = ap[0], p1 = ap[1], p2 = ap[2], p3 = ap[3];
            const ulonglong2 q  = *reinterpret_cast<const ulonglong2*>(&pwi[cp * WQ + wofs]);
            ffma2(acc[0][0], p0.x, q.x); ffma2(acc[0][1], p0.x, q.y);
            ffma2(acc[1][0], p0.y, q.x); ffma2(acc[1][1], p0.y, q.y);
            ffma2(acc[2][0], p1.x, q.x); ffma2(acc[2][1], p1.x, q.y);
            ffma2(acc[3][0], p1.y, q.x); ffma2(acc[3][1], p1.y, q.y);
            ffma2(acc[4][0], p2.x, q.x); ffma2(acc[4][1], p2.x, q.y);
            ffma2(acc[5][0], p2.y, q.x); ffma2(acc[5][1], p2.y, q.y);
            ffma2(acc[6][0], p3.x, q.x); ffma2(acc[6][1], p3.x, q.y);
            ffma2(acc[7][0], p3.y, q.x); ffma2(acc[7][1], p3.y, q.y);
        }

        #pragma unroll
        for (int oi = 0; oi < 8; oi++) {
            const int o = o0 + oi;
            const float bo = be_[oi];
            const size_t base = (((size_t)(n * PC + o)) * HH + h) * WW + wq * WQ + wofs;
            const float2 xv = *reinterpret_cast<const float2*>(x + base);
            float e0, e1, t0, t1;
            upk2(acc[oi][0], e0, e1); t0 = e0 + e1 + bo;
            upk2(acc[oi][1], e0, e1); t1 = e0 + e1 + bo;
            float2 r;
            r.x = xv.x * (1.0f + sigf(t0));
            r.y = xv.y * (1.0f + sigf(t1));
            *reinterpret_cast<float2*>(out + base) = r;
        }
    }
}

extern "C" void kernel_launch(void* const* d_in, const int* in_sizes, int n_in,
                              void* d_out, int out_size) {
    const float* x   = (const float*)d_in[0];
    const float* w_h = (const float*)d_in[1];
    const float* b_h = (const float*)d_in[2];
    const float* w_w = (const float*)d_in[3];
    const float* b_w = (const float*)d_in[4];
    const float* w_e = (const float*)d_in[5];
    const float* b_e = (const float*)d_in[6];
    float* out = (float*)d_out;

    const int smem23 = (2 * PC * WW + 8 * PC * 6) * 4;       // 137216
    const int smem4  = NCP * WQ * 8 + HB * NCP * PC * 8;     // 16384 + 16384 = 32768
    cudaFuncSetAttribute(k23,      cudaFuncAttributeMaxDynamicSharedMemorySize, smem23);
    cudaFuncSetAttribute(k4_apply, cudaFuncAttributeMaxDynamicSharedMemorySize, smem4);

    k1_stats<<<NP * PC, 256>>>(x);
    k23<<<64 + NP * 4, 256, smem23>>>(w_h, b_h, w_w, b_w);
    k4_apply<<<NP * 16 * 4, 256, smem4>>>(x, w_e, b_e, out);
}

// round 9
// speedup vs baseline: 1.1894x; 1.1894x over previous
#include <cuda_runtime.h>

// Problem constants
#define NP    64     // B*NUM_PARTS = 16*4
#define PC    32     // channels per part
#define HH    64
#define WW    512
#define HB    4      // h rows per K4 CTA
#define WH    256    // w half width per K4 CTA

typedef unsigned long long u64;

__device__ __forceinline__ u64 pk2(float a, float b) {
    u64 r; asm("mov.b64 %0, {%1,%2};" : "=l"(r) : "f"(a), "f"(b)); return r;
}
__device__ __forceinline__ void upk2(u64 v, float& a, float& b) {
    asm("mov.b64 {%0,%1}, %2;" : "=f"(a), "=f"(b) : "l"(v));
}
__device__ __forceinline__ void ffma2(u64& d, u64 a, u64 b) {
    asm("fma.rn.f32x2 %0, %1, %2, %0;" : "+l"(d) : "l"(a), "l"(b));
}

// branchless sigmoid: 2 MUFU ops, no divergence, ~2^-21 accuracy
__device__ __forceinline__ float sigf(float t) {
    float e = __expf(-fabsf(t));
    float s = __fdividef(1.0f, 1.0f + e);   // sigmoid(|t|)
    return (t >= 0.0f) ? s : 1.0f - s;
}

// Scratch (device globals, allocation-free)
__device__ float g_havg[NP * PC * HH];
__device__ float g_hmax[NP * PC * HH];
__device__ float g_wavg[NP * PC * WW];
__device__ float g_wmax[NP * PC * WW];
__device__ float g_ph[NP * PC * HH];
__device__ float g_pw[NP * PC * WW];

// ---------------------------------------------------------------------------
// K1: per-(n,c) slice stats. Quad-level shfl reduce + smem partials.
// grid 2048, 256 threads
// ---------------------------------------------------------------------------
__global__ __launch_bounds__(256) void k1_stats(const float* __restrict__ x) {
    const int nc  = blockIdx.x;
    const int tid = threadIdx.x;
    const int r2  = tid >> 7;        // 0/1: which row of a 2-row stripe
    const int c4  = tid & 127;       // float4 column 0..127

    const float4* xs = reinterpret_cast<const float4*>(x + (size_t)nc * HH * WW);

    __shared__ float rs[HH][33], rm[HH][33];   // 33: kill final-reduce bank conflict
    __shared__ float csh[WW], cmh[WW];

    float cs0 = 0.f, cs1 = 0.f, cs2 = 0.f, cs3 = 0.f;
    float cm0 = -3.4e38f, cm1 = -3.4e38f, cm2 = -3.4e38f, cm3 = -3.4e38f;
    const int q = c4 >> 2;

    for (int h0 = 0; h0 < HH; h0 += 2) {
        const int h = h0 + r2;
        float4 v = xs[h * 128 + c4];
        cs0 += v.x; cs1 += v.y; cs2 += v.z; cs3 += v.w;
        cm0 = fmaxf(cm0, v.x); cm1 = fmaxf(cm1, v.y);
        cm2 = fmaxf(cm2, v.z); cm3 = fmaxf(cm3, v.w);
        float s = (v.x + v.y) + (v.z + v.w);
        float m = fmaxf(fmaxf(v.x, v.y), fmaxf(v.z, v.w));
        s += __shfl_xor_sync(0xffffffffu, s, 1);
        m  = fmaxf(m, __shfl_xor_sync(0xffffffffu, m, 1));
        s += __shfl_xor_sync(0xffffffffu, s, 2);
        m  = fmaxf(m, __shfl_xor_sync(0xffffffffu, m, 2));
        if ((tid & 3) == 0) { rs[h][q] = s; rm[h][q] = m; }
    }
    __syncthreads();

    if (tid < HH) {
        float s = 0.f, m = -3.4e38f;
        #pragma unroll
        for (int k = 0; k < 32; k++) { s += rs[tid][k]; m = fmaxf(m, rm[tid][k]); }
        g_havg[nc * HH + tid] = s * (1.0f / (float)WW);
        g_hmax[nc * HH + tid] = m;
    }

    if (r2 == 0) {
        csh[c4 * 4 + 0] = cs0; csh[c4 * 4 + 1] = cs1; csh[c4 * 4 + 2] = cs2; csh[c4 * 4 + 3] = cs3;
        cmh[c4 * 4 + 0] = cm0; cmh[c4 * 4 + 1] = cm1; cmh[c4 * 4 + 2] = cm2; cmh[c4 * 4 + 3] = cm3;
    }
    __syncthreads();
    if (r2 == 1) {
        const int w = c4 * 4;
        g_wavg[nc * WW + w + 0] = (cs0 + csh[w + 0]) * (1.0f / (float)HH);
        g_wavg[nc * WW + w + 1] = (cs1 + csh[w + 1]) * (1.0f / (float)HH);
        g_wavg[nc * WW + w + 2] = (cs2 + csh[w + 2]) * (1.0f / (float)HH);
        g_wavg[nc * WW + w + 3] = (cs3 + csh[w + 3]) * (1.0f / (float)HH);
        g_wmax[nc * WW + w + 0] = fmaxf(cm0, cmh[w + 0]);
        g_wmax[nc * WW + w + 1] = fmaxf(cm1, cmh[w + 1]);
        g_wmax[nc * WW + w + 2] = fmaxf(cm2, cmh[w + 2]);
        g_wmax[nc * WW + w + 3] = fmaxf(cm3, cmh[w + 3]);
    }
}

// ---------------------------------------------------------------------------
// K23: merged ph conv (blocks [0,64)) + pw conv (blocks [64,320), o split 4-way)
// 256 threads. dynamic smem: k3-part needs 34304 floats = 137216 B
// ---------------------------------------------------------------------------
__global__ __launch_bounds__(256) void k23(const float* __restrict__ w_h,
                                           const float* __restrict__ b_h,
                                           const float* __restrict__ w_w,
                                           const float* __restrict__ b_w) {
    extern __shared__ float sm[];
    const int bid = blockIdx.x;
    const int tid = threadIdx.x;

    if (bid < 64) {
        // ---------------- ph: conv 3x2 pad(h)=1 + relu + softmax over h ----
        const int n = bid;
        float* ha = sm;                 // [32][64]
        float* hm = sm + PC * HH;       // [32][64]
        float* wh = sm + 2 * PC * HH;   // 6144

        for (int idx = tid; idx < PC * HH; idx += 256) {
            ha[idx] = g_havg[n * PC * HH + idx];
            hm[idx] = g_hmax[n * PC * HH + idx];
        }
        for (int idx = tid; idx < PC * PC * 6; idx += 256) wh[idx] = w_h[idx];
        __syncthreads();

        const int o  = tid >> 3;     // 0..31
        const int j  = tid & 7;      // 8 threads per o, 8 h each
        const int hb = j * 8;

        float acc[8];
        const float bo = b_h[o];
        #pragma unroll
        for (int t = 0; t < 8; t++) acc[t] = bo;

        for (int i = 0; i < PC; i++) {
            const float* wp = &wh[(o * PC + i) * 6];
            const float w00 = wp[0], w01 = wp[1], w10 = wp[2], w11 = wp[3], w20 = wp[4], w21 = wp[5];
            const float* A = ha + i * HH;
            const float* M = hm + i * HH;
            float wA[10], wM[10];
            wA[0] = (hb > 0) ? A[hb - 1] : 0.f;
            wM[0] = (hb > 0) ? M[hb - 1] : 0.f;
            #pragma unroll
            for (int t = 0; t < 8; t++) { wA[t + 1] = A[hb + t]; wM[t + 1] = M[hb + t]; }
            wA[9] = (hb + 8 < HH) ? A[hb + 8] : 0.f;
            wM[9] = (hb + 8 < HH) ? M[hb + 8] : 0.f;
            #pragma unroll
            for (int t = 0; t < 8; t++) {
                acc[t] += wA[t] * w00 + wM[t] * w01
                        + wA[t + 1] * w10 + wM[t + 1] * w11
                        + wA[t + 2] * w20 + wM[t + 2] * w21;
            }
        }

        float lm = -3.4e38f;
        #pragma unroll
        for (int t = 0; t < 8; t++) { acc[t] = fmaxf(acc[t], 0.f); lm = fmaxf(lm, acc[t]); }
        #pragma unroll
        for (int off = 1; off <= 4; off <<= 1) lm = fmaxf(lm, __shfl_xor_sync(0xffffffffu, lm, off));
        float ls = 0.f;
        #pragma unroll
        for (int t = 0; t < 8; t++) { acc[t] = __expf(acc[t] - lm); ls += acc[t]; }
        #pragma unroll
        for (int off = 1; off <= 4; off <<= 1) ls += __shfl_xor_sync(0xffffffffu, ls, off);
        const float inv = 1.0f / ls;
        #pragma unroll
        for (int t = 0; t < 8; t++) g_ph[(n * PC + o) * HH + hb + t] = acc[t] * inv;
    } else {
        // ---------------- pw: conv 2x3 pad(w)=1 + relu + softmax over w ----
        const int b2 = bid - 64;
        const int n  = b2 >> 2;
        const int og = b2 & 3;          // o group of 8

        float* wa = sm;                  // [32][512]
        float* wm = sm + PC * WW;        // [32][512]
        float* ww = sm + 2 * PC * WW;    // 8*32*6 = 1536

        {
            const float4* sa = reinterpret_cast<const float4*>(g_wavg + n * PC * WW);
            const float4* sx = reinterpret_cast<const float4*>(g_wmax + n * PC * WW);
            float4* da = reinterpret_cast<float4*>(wa);
            float4* dm = reinterpret_cast<float4*>(wm);
            for (int idx = tid; idx < PC * WW / 4; idx += 256) { da[idx] = sa[idx]; dm[idx] = sx[idx]; }
        }
        {
            const float* src = w_w + og * 8 * PC * 6;
            for (int idx = tid; idx < 8 * PC * 6; idx += 256) ww[idx] = src[idx];
        }
        __syncthreads();

        const int oo = tid >> 5;            // 0..7 within group
        const int o  = og * 8 + oo;
        const int j  = tid & 31;            // one warp per o

        float acc[16];
        const float bo = b_w[o];
        #pragma unroll
        for (int t = 0; t < 16; t++) acc[t] = bo;

        for (int i = 0; i < PC; i++) {
            const float* wp = &ww[(oo * PC + i) * 6];
            const float a0 = wp[0], a1 = wp[1], a2 = wp[2];
            const float m0 = wp[3], m1 = wp[4], m2 = wp[5];
            const float* A = wa + i * WW;
            const float* M = wm + i * WW;
            #pragma unroll
            for (int k = 0; k < 4; k++) {
                const int w0 = j * 4 + k * 128;
                float4 av = *reinterpret_cast<const float4*>(&A[w0]);
                float4 mv = *reinterpret_cast<const float4*>(&M[w0]);
                float am1 = (w0 > 0) ? A[w0 - 1] : 0.f;
                float mm1 = (w0 > 0) ? M[w0 - 1] : 0.f;
                float ap4 = (w0 + 4 < WW) ? A[w0 + 4] : 0.f;
                float mp4 = (w0 + 4 < WW) ? M[w0 + 4] : 0.f;
                acc[k*4+0] += am1 * a0 + av.x * a1 + av.y * a2 + mm1 * m0 + mv.x * m1 + mv.y * m2;
                acc[k*4+1] += av.x * a0 + av.y * a1 + av.z * a2 + mv.x * m0 + mv.y * m1 + mv.z * m2;
                acc[k*4+2] += av.y * a0 + av.z * a1 + av.w * a2 + mv.y * m0 + mv.z * m1 + mv.w * m2;
                acc[k*4+3] += av.z * a0 + av.w * a1 + ap4 * a2 + mv.z * m0 + mv.w * m1 + mp4 * m2;
            }
        }

        float lm = -3.4e38f;
        #pragma unroll
        for (int t = 0; t < 16; t++) { acc[t] = fmaxf(acc[t], 0.f); lm = fmaxf(lm, acc[t]); }
        #pragma unroll
        for (int off = 1; off <= 16; off <<= 1) lm = fmaxf(lm, __shfl_xor_sync(0xffffffffu, lm, off));
        float ls = 0.f;
        #pragma unroll
        for (int t = 0; t < 16; t++) { acc[t] = __expf(acc[t] - lm); ls += acc[t]; }
        #pragma unroll
        for (int off = 1; off <= 16; off <<= 1) ls += __shfl_xor_sync(0xffffffffu, ls, off);
        const float inv = 1.0f / ls;

        float* dst = g_pw + (n * PC + o) * WW;
        #pragma unroll
        for (int k = 0; k < 4; k++) {
            const int w0 = j * 4 + k * 128;
            float4 r;
            r.x = acc[k*4+0] * inv; r.y = acc[k*4+1] * inv;
            r.z = acc[k*4+2] * inv; r.w = acc[k*4+3] * inv;
            *reinterpret_cast<float4*>(&dst[w0]) = r;
        }
    }
}

// ---------------------------------------------------------------------------
// K4: apply. R5 (253us) mainloop verbatim: coalesced epilogue mapping, float At
// with pk2 in the loop (2 broadcast LDS + 1 data LDS + 8 MOV + 16 FFMA2/iter —
// the crossbar/issue sweet spot). Only change vs R5: depth-2 x prefetch in the
// epilogue + hoisted biases, to hide the ~600cyc LDG dependency.
// dyn smem: pw[32][256] + At4[4][32][32] = 48KB, 3 CTAs/SM
// ---------------------------------------------------------------------------
__global__ __launch_bounds__(256, 3) void k4_apply(const float* __restrict__ x,
                                                   const float* __restrict__ w_e,
                                                   const float* __restrict__ b_e,
                                                   float* __restrict__ out) {
    extern __shared__ float sm4[];
    float* pws = sm4;             // [32][256]
    float* At4 = sm4 + PC * WH;   // [4][c][o]
    __shared__ float phs[HB * PC];

    const int bid = blockIdx.x;
    const int n   = bid >> 5;
    const int hb  = (bid >> 1) & 15;   // h = hb*4 + hl
    const int wh  = bid & 1;           // w half
    const int tid = threadIdx.x;

    // stage pw half tile
    {
        const float4* pwg = reinterpret_cast<const float4*>(g_pw + n * PC * WW) + wh * (WH / 4);
        float4* pw4 = reinterpret_cast<float4*>(pws);
        for (int idx = tid; idx < PC * WH / 4; idx += 256) {
            const int c = idx >> 6, col = idx & 63;
            pw4[idx] = pwg[c * (WW / 4) + col];
        }
    }
    if (tid < HB * PC) {
        const int hl = tid >> 5, c = tid & 31;
        phs[tid] = g_ph[(n * PC + c) * HH + hb * HB + hl];
    }
    __syncthreads();

    for (int idx = tid; idx < HB * PC * PC; idx += 256) {
        const int hl = idx >> 10;
        const int c  = (idx >> 5) & 31;
        const int o  = idx & 31;
        At4[idx] = w_e[o * PC + c] * phs[hl * PC + c];
    }
    __syncthreads();

    const int wid  = tid >> 5;            // 0..7
    const int lane = tid & 31;
    const int o0   = (wid & 3) * 8;       // 8 contiguous o per warp
    const int wofs = (wid >> 2) * 128 + lane * 4;   // contiguous w within half

    // hoisted biases
    const float4 beL = *reinterpret_cast<const float4*>(&b_e[o0]);
    const float4 beH = *reinterpret_cast<const float4*>(&b_e[o0 + 4]);
    const float be_[8] = { beL.x, beL.y, beL.z, beL.w, beH.x, beH.y, beH.z, beH.w };

    #pragma unroll 1
    for (int hl = 0; hl < HB; hl++) {
        const int h = hb * HB + hl;
        const float* At = At4 + hl * (PC * PC);

        u64 acc[8][2];
        #pragma unroll
        for (int oi = 0; oi < 8; oi++) { acc[oi][0] = 0ull; acc[oi][1] = 0ull; }

        #pragma unroll 4
        for (int c = 0; c < PC; c++) {
            const float4 a0 = *reinterpret_cast<const float4*>(&At[c * PC + o0]);
            const float4 a1 = *reinterpret_cast<const float4*>(&At[c * PC + o0 + 4]);
            const ulonglong2 q = *reinterpret_cast<const ulonglong2*>(&pws[c * WH + wofs]);
            u64 av;
            av = pk2(a0.x, a0.x); ffma2(acc[0][0], av, q.x); ffma2(acc[0][1], av, q.y);
            av = pk2(a0.y, a0.y); ffma2(acc[1][0], av, q.x); ffma2(acc[1][1], av, q.y);
            av = pk2(a0.z, a0.z); ffma2(acc[2][0], av, q.x); ffma2(acc[2][1], av, q.y);
            av = pk2(a0.w, a0.w); ffma2(acc[3][0], av, q.x); ffma2(acc[3][1], av, q.y);
            av = pk2(a1.x, a1.x); ffma2(acc[4][0], av, q.x); ffma2(acc[4][1], av, q.y);
            av = pk2(a1.y, a1.y); ffma2(acc[5][0], av, q.x); ffma2(acc[5][1], av, q.y);
            av = pk2(a1.z, a1.z); ffma2(acc[6][0], av, q.x); ffma2(acc[6][1], av, q.y);
            av = pk2(a1.w, a1.w); ffma2(acc[7][0], av, q.x); ffma2(acc[7][1], av, q.y);
        }

        // epilogue with 2-deep x prefetch
        const size_t base0 = (((size_t)(n * PC + o0)) * HH + h) * WW + wh * WH + wofs;
        float4 xv0 = *reinterpret_cast<const float4*>(x + base0);
        float4 xv1 = *reinterpret_cast<const float4*>(x + base0 + (size_t)HH * WW);

        #pragma unroll
        for (int oi = 0; oi < 8; oi++) {
            const float4 xv = xv0;
            xv0 = xv1;
            if (oi < 6) xv1 = *reinterpret_cast<const float4*>(x + base0 + (size_t)(oi + 2) * HH * WW);
            const float bo = be_[oi];
            float t0, t1, t2, t3;
            upk2(acc[oi][0], t0, t1);
            upk2(acc[oi][1], t2, t3);
            float4 r;
            r.x = xv.x * (1.0f + sigf(t0 + bo));
            r.y = xv.y * (1.0f + sigf(t1 + bo));
            r.z = xv.z * (1.0f + sigf(t2 + bo));
            r.w = xv.w * (1.0f + sigf(t3 + bo));
            *reinterpret_cast<float4*>(out + base0 + (size_t)oi * HH * WW) = r;
        }
    }
}

extern "C" void kernel_launch(void* const* d_in, const int* in_sizes, int n_in,
                              void* d_out, int out_size) {
    const float* x   = (const float*)d_in[0];
    const float* w_h = (const float*)d_in[1];
    const float* b_h = (const float*)d_in[2];
    const float* w_w = (const float*)d_in[3];
    const float* b_w = (const float*)d_in[4];
    const float* w_e = (const float*)d_in[5];
    const float* b_e = (const float*)d_in[6];
    float* out = (float*)d_out;

    const int smem23 = (2 * PC * WW + 8 * PC * 6) * 4;   // 137216
    const int smem4  = (PC * WH + HB * PC * PC) * 4;     // 49152
    cudaFuncSetAttribute(k23,      cudaFuncAttributeMaxDynamicSharedMemorySize, smem23);
    cudaFuncSetAttribute(k4_apply, cudaFuncAttributeMaxDynamicSharedMemorySize, smem4);

    k1_stats<<<NP * PC, 256>>>(x);
    k23<<<64 + NP * 4, 256, smem23>>>(w_h, b_h, w_w, b_w);
    k4_apply<<<NP * 16 * 2, 256, smem4>>>(x, w_e, b_e, out);
}

// round 10
// speedup vs baseline: 1.2963x; 1.0898x over previous
#include <cuda_runtime.h>

// Problem constants
#define NP    64     // B*NUM_PARTS = 16*4
#define PC    32     // channels per part
#define HH    64
#define WW    512
#define HB    8      // h rows per K4 CTA
#define WH    256    // w half width per K4 CTA

typedef unsigned long long u64;

__device__ __forceinline__ u64 pk2(float a, float b) {
    u64 r; asm("mov.b64 %0, {%1,%2};" : "=l"(r) : "f"(a), "f"(b)); return r;
}
__device__ __forceinline__ void upk2(u64 v, float& a, float& b) {
    asm("mov.b64 {%0,%1}, %2;" : "=f"(a), "=f"(b) : "l"(v));
}
__device__ __forceinline__ void ffma2(u64& d, u64 a, u64 b) {
    asm("fma.rn.f32x2 %0, %1, %2, %0;" : "+l"(d) : "l"(a), "l"(b));
}

// branchless sigmoid: 2 MUFU ops, no divergence, ~2^-21 accuracy
__device__ __forceinline__ float sigf(float t) {
    float e = __expf(-fabsf(t));
    float s = __fdividef(1.0f, 1.0f + e);   // sigmoid(|t|)
    return (t >= 0.0f) ? s : 1.0f - s;
}

// Scratch (device globals, allocation-free)
__device__ float g_havg[NP * PC * HH];
__device__ float g_hmax[NP * PC * HH];
__device__ float g_wavg[NP * PC * WW];
__device__ float g_wmax[NP * PC * WW];
__device__ float g_ph[NP * PC * HH];
__device__ float g_pw[NP * PC * WW];

// ---------------------------------------------------------------------------
// K1: per-(n,c) slice stats. Quad-level shfl reduce + smem partials.
// grid 2048, 256 threads
// ---------------------------------------------------------------------------
__global__ __launch_bounds__(256) void k1_stats(const float* __restrict__ x) {
    const int nc  = blockIdx.x;
    const int tid = threadIdx.x;
    const int r2  = tid >> 7;        // 0/1: which row of a 2-row stripe
    const int c4  = tid & 127;       // float4 column 0..127

    const float4* xs = reinterpret_cast<const float4*>(x + (size_t)nc * HH * WW);

    __shared__ float rs[HH][33], rm[HH][33];   // 33: kill final-reduce bank conflict
    __shared__ float csh[WW], cmh[WW];

    float cs0 = 0.f, cs1 = 0.f, cs2 = 0.f, cs3 = 0.f;
    float cm0 = -3.4e38f, cm1 = -3.4e38f, cm2 = -3.4e38f, cm3 = -3.4e38f;
    const int q = c4 >> 2;

    for (int h0 = 0; h0 < HH; h0 += 2) {
        const int h = h0 + r2;
        float4 v = xs[h * 128 + c4];
        cs0 += v.x; cs1 += v.y; cs2 += v.z; cs3 += v.w;
        cm0 = fmaxf(cm0, v.x); cm1 = fmaxf(cm1, v.y);
        cm2 = fmaxf(cm2, v.z); cm3 = fmaxf(cm3, v.w);
        float s = (v.x + v.y) + (v.z + v.w);
        float m = fmaxf(fmaxf(v.x, v.y), fmaxf(v.z, v.w));
        s += __shfl_xor_sync(0xffffffffu, s, 1);
        m  = fmaxf(m, __shfl_xor_sync(0xffffffffu, m, 1));
        s += __shfl_xor_sync(0xffffffffu, s, 2);
        m  = fmaxf(m, __shfl_xor_sync(0xffffffffu, m, 2));
        if ((tid & 3) == 0) { rs[h][q] = s; rm[h][q] = m; }
    }
    __syncthreads();

    if (tid < HH) {
        float s = 0.f, m = -3.4e38f;
        #pragma unroll
        for (int k = 0; k < 32; k++) { s += rs[tid][k]; m = fmaxf(m, rm[tid][k]); }
        g_havg[nc * HH + tid] = s * (1.0f / (float)WW);
        g_hmax[nc * HH + tid] = m;
    }

    if (r2 == 0) {
        csh[c4 * 4 + 0] = cs0; csh[c4 * 4 + 1] = cs1; csh[c4 * 4 + 2] = cs2; csh[c4 * 4 + 3] = cs3;
        cmh[c4 * 4 + 0] = cm0; cmh[c4 * 4 + 1] = cm1; cmh[c4 * 4 + 2] = cm2; cmh[c4 * 4 + 3] = cm3;
    }
    __syncthreads();
    if (r2 == 1) {
        const int w = c4 * 4;
        g_wavg[nc * WW + w + 0] = (cs0 + csh[w + 0]) * (1.0f / (float)HH);
        g_wavg[nc * WW + w + 1] = (cs1 + csh[w + 1]) * (1.0f / (float)HH);
        g_wavg[nc * WW + w + 2] = (cs2 + csh[w + 2]) * (1.0f / (float)HH);
        g_wavg[nc * WW + w + 3] = (cs3 + csh[w + 3]) * (1.0f / (float)HH);
        g_wmax[nc * WW + w + 0] = fmaxf(cm0, cmh[w + 0]);
        g_wmax[nc * WW + w + 1] = fmaxf(cm1, cmh[w + 1]);
        g_wmax[nc * WW + w + 2] = fmaxf(cm2, cmh[w + 2]);
        g_wmax[nc * WW + w + 3] = fmaxf(cm3, cmh[w + 3]);
    }
}

// ---------------------------------------------------------------------------
// K23: merged ph conv (blocks [0,64)) + pw conv (blocks [64,320), o split 4-way)
// 256 threads. dynamic smem: k3-part needs 34304 floats = 137216 B
// ---------------------------------------------------------------------------
__global__ __launch_bounds__(256) void k23(const float* __restrict__ w_h,
                                           const float* __restrict__ b_h,
                                           const float* __restrict__ w_w,
                                           const float* __restrict__ b_w) {
    extern __shared__ float sm[];
    const int bid = blockIdx.x;
    const int tid = threadIdx.x;

    if (bid < 64) {
        // ---------------- ph: conv 3x2 pad(h)=1 + relu + softmax over h ----
        const int n = bid;
        float* ha = sm;                 // [32][64]
        float* hm = sm + PC * HH;       // [32][64]
        float* wh = sm + 2 * PC * HH;   // 6144

        for (int idx = tid; idx < PC * HH; idx += 256) {
            ha[idx] = g_havg[n * PC * HH + idx];
            hm[idx] = g_hmax[n * PC * HH + idx];
        }
        for (int idx = tid; idx < PC * PC * 6; idx += 256) wh[idx] = w_h[idx];
        __syncthreads();

        const int o  = tid >> 3;     // 0..31
        const int j  = tid & 7;      // 8 threads per o, 8 h each
        const int hb = j * 8;

        float acc[8];
        const float bo = b_h[o];
        #pragma unroll
        for (int t = 0; t < 8; t++) acc[t] = bo;

        for (int i = 0; i < PC; i++) {
            const float* wp = &wh[(o * PC + i) * 6];
            const float w00 = wp[0], w01 = wp[1], w10 = wp[2], w11 = wp[3], w20 = wp[4], w21 = wp[5];
            const float* A = ha + i * HH;
            const float* M = hm + i * HH;
            float wA[10], wM[10];
            wA[0] = (hb > 0) ? A[hb - 1] : 0.f;
            wM[0] = (hb > 0) ? M[hb - 1] : 0.f;
            #pragma unroll
            for (int t = 0; t < 8; t++) { wA[t + 1] = A[hb + t]; wM[t + 1] = M[hb + t]; }
            wA[9] = (hb + 8 < HH) ? A[hb + 8] : 0.f;
            wM[9] = (hb + 8 < HH) ? M[hb + 8] : 0.f;
            #pragma unroll
            for (int t = 0; t < 8; t++) {
                acc[t] += wA[t] * w00 + wM[t] * w01
                        + wA[t + 1] * w10 + wM[t + 1] * w11
                        + wA[t + 2] * w20 + wM[t + 2] * w21;
            }
        }

        float lm = -3.4e38f;
        #pragma unroll
        for (int t = 0; t < 8; t++) { acc[t] = fmaxf(acc[t], 0.f); lm = fmaxf(lm, acc[t]); }
        #pragma unroll
        for (int off = 1; off <= 4; off <<= 1) lm = fmaxf(lm, __shfl_xor_sync(0xffffffffu, lm, off));
        float ls = 0.f;
        #pragma unroll
        for (int t = 0; t < 8; t++) { acc[t] = __expf(acc[t] - lm); ls += acc[t]; }
        #pragma unroll
        for (int off = 1; off <= 4; off <<= 1) ls += __shfl_xor_sync(0xffffffffu, ls, off);
        const float inv = 1.0f / ls;
        #pragma unroll
        for (int t = 0; t < 8; t++) g_ph[(n * PC + o) * HH + hb + t] = acc[t] * inv;
    } else {
        // ---------------- pw: conv 2x3 pad(w)=1 + relu + softmax over w ----
        const int b2 = bid - 64;
        const int n  = b2 >> 2;
        const int og = b2 & 3;          // o group of 8

        float* wa = sm;                  // [32][512]
        float* wm = sm + PC * WW;        // [32][512]
        float* ww = sm + 2 * PC * WW;    // 8*32*6 = 1536

        {
            const float4* sa = reinterpret_cast<const float4*>(g_wavg + n * PC * WW);
            const float4* sx = reinterpret_cast<const float4*>(g_wmax + n * PC * WW);
            float4* da = reinterpret_cast<float4*>(wa);
            float4* dm = reinterpret_cast<float4*>(wm);
            for (int idx = tid; idx < PC * WW / 4; idx += 256) { da[idx] = sa[idx]; dm[idx] = sx[idx]; }
        }
        {
            const float* src = w_w + og * 8 * PC * 6;
            for (int idx = tid; idx < 8 * PC * 6; idx += 256) ww[idx] = src[idx];
        }
        __syncthreads();

        const int oo = tid >> 5;            // 0..7 within group
        const int o  = og * 8 + oo;
        const int j  = tid & 31;            // one warp per o

        float acc[16];
        const float bo = b_w[o];
        #pragma unroll
        for (int t = 0; t < 16; t++) acc[t] = bo;

        for (int i = 0; i < PC; i++) {
            const float* wp = &ww[(oo * PC + i) * 6];
            const float a0 = wp[0], a1 = wp[1], a2 = wp[2];
            const float m0 = wp[3], m1 = wp[4], m2 = wp[5];
            const float* A = wa + i * WW;
            const float* M = wm + i * WW;
            #pragma unroll
            for (int k = 0; k < 4; k++) {
                const int w0 = j * 4 + k * 128;
                float4 av = *reinterpret_cast<const float4*>(&A[w0]);
                float4 mv = *reinterpret_cast<const float4*>(&M[w0]);
                float am1 = (w0 > 0) ? A[w0 - 1] : 0.f;
                float mm1 = (w0 > 0) ? M[w0 - 1] : 0.f;
                float ap4 = (w0 + 4 < WW) ? A[w0 + 4] : 0.f;
                float mp4 = (w0 + 4 < WW) ? M[w0 + 4] : 0.f;
                acc[k*4+0] += am1 * a0 + av.x * a1 + av.y * a2 + mm1 * m0 + mv.x * m1 + mv.y * m2;
                acc[k*4+1] += av.x * a0 + av.y * a1 + av.z * a2 + mv.x * m0 + mv.y * m1 + mv.z * m2;
                acc[k*4+2] += av.y * a0 + av.z * a1 + av.w * a2 + mv.y * m0 + mv.z * m1 + mv.w * m2;
                acc[k*4+3] += av.z * a0 + av.w * a1 + ap4 * a2 + mv.z * m0 + mv.w * m1 + mp4 * m2;
            }
        }

        float lm = -3.4e38f;
        #pragma unroll
        for (int t = 0; t < 16; t++) { acc[t] = fmaxf(acc[t], 0.f); lm = fmaxf(lm, acc[t]); }
        #pragma unroll
        for (int off = 1; off <= 16; off <<= 1) lm = fmaxf(lm, __shfl_xor_sync(0xffffffffu, lm, off));
        float ls = 0.f;
        #pragma unroll
        for (int t = 0; t < 16; t++) { acc[t] = __expf(acc[t] - lm); ls += acc[t]; }
        #pragma unroll
        for (int off = 1; off <= 16; off <<= 1) ls += __shfl_xor_sync(0xffffffffu, ls, off);
        const float inv = 1.0f / ls;

        float* dst = g_pw + (n * PC + o) * WW;
        #pragma unroll
        for (int k = 0; k < 4; k++) {
            const int w0 = j * 4 + k * 128;
            float4 r;
            r.x = acc[k*4+0] * inv; r.y = acc[k*4+1] * inv;
            r.z = acc[k*4+2] * inv; r.w = acc[k*4+3] * inv;
            *reinterpret_cast<float4*>(&dst[w0]) = r;
        }
    }
}

// ---------------------------------------------------------------------------
// K4: apply. One CTA per (n, h-block of 8, w-half). Proven 252us mainloop
// (2 broadcast LDS + 1 data LDS + 8 MOV + 16 FFMA2 per c-iter). Changes:
//  - HB=8: pw tile staged once per 8 h (staging traffic halved)
//  - L2 prefetch of this hl's x tile BEFORE the c-loop (no reg cost); the
//    ~1000cyc fma-bound c-loop covers the DRAM trip, epilogue LDGs hit L2.
// dyn smem: pw[32][256] (32KB) + At8[8][32][32] (32KB) = 64KB, 3 CTAs/SM
// ---------------------------------------------------------------------------
__global__ __launch_bounds__(256, 3) void k4_apply(const float* __restrict__ x,
                                                   const float* __restrict__ w_e,
                                                   const float* __restrict__ b_e,
                                                   float* __restrict__ out) {
    extern __shared__ float sm4[];
    float* pws = sm4;             // [32][256]
    float* At8 = sm4 + PC * WH;   // [8][c][o]
    __shared__ float phs[HB * PC];

    const int bid = blockIdx.x;
    const int n   = bid >> 4;
    const int hbb = (bid >> 1) & 7;    // h = hbb*8 + hl
    const int wh  = bid & 1;           // w half
    const int tid = threadIdx.x;

    // stage pw half tile
    {
        const float4* pwg = reinterpret_cast<const float4*>(g_pw + n * PC * WW) + wh * (WH / 4);
        float4* pw4 = reinterpret_cast<float4*>(pws);
        for (int idx = tid; idx < PC * WH / 4; idx += 256) {
            const int c = idx >> 6, col = idx & 63;
            pw4[idx] = pwg[c * (WW / 4) + col];
        }
    }
    {
        const int hl = tid >> 5, c = tid & 31;   // 256 = 8*32 exactly
        phs[tid] = g_ph[(n * PC + c) * HH + hbb * HB + hl];
    }
    __syncthreads();

    for (int idx = tid; idx < HB * PC * PC; idx += 256) {
        const int hl = idx >> 10;
        const int c  = (idx >> 5) & 31;
        const int o  = idx & 31;
        At8[idx] = w_e[o * PC + c] * phs[hl * PC + c];
    }
    __syncthreads();

    const int wid  = tid >> 5;            // 0..7
    const int lane = tid & 31;
    const int o0   = (wid & 3) * 8;       // 8 contiguous o per warp
    const int wofs = (wid >> 2) * 128 + lane * 4;   // contiguous w within half

    // hoisted biases
    const float4 beL = *reinterpret_cast<const float4*>(&b_e[o0]);
    const float4 beH = *reinterpret_cast<const float4*>(&b_e[o0 + 4]);
    const float be_[8] = { beL.x, beL.y, beL.z, beL.w, beH.x, beH.y, beH.z, beH.w };

    #pragma unroll 1
    for (int hl = 0; hl < HB; hl++) {
        const int h = hbb * HB + hl;
        const float* At = At8 + hl * (PC * PC);
        const size_t base0 = (((size_t)(n * PC + o0)) * HH + h) * WW + wh * WH + wofs;

        // L2 prefetch of this hl's x tile; covered by the c-loop below
        #pragma unroll
        for (int oi = 0; oi < 8; oi++)
            asm volatile("prefetch.global.L2 [%0];" :: "l"(x + base0 + (size_t)oi * HH * WW));

        u64 acc[8][2];
        #pragma unroll
        for (int oi = 0; oi < 8; oi++) { acc[oi][0] = 0ull; acc[oi][1] = 0ull; }

        #pragma unroll 4
        for (int c = 0; c < PC; c++) {
            const float4 a0 = *reinterpret_cast<const float4*>(&At[c * PC + o0]);
            const float4 a1 = *reinterpret_cast<const float4*>(&At[c * PC + o0 + 4]);
            const ulonglong2 q = *reinterpret_cast<const ulonglong2*>(&pws[c * WH + wofs]);
            u64 av;
            av = pk2(a0.x, a0.x); ffma2(acc[0][0], av, q.x); ffma2(acc[0][1], av, q.y);
            av = pk2(a0.y, a0.y); ffma2(acc[1][0], av, q.x); ffma2(acc[1][1], av, q.y);
            av = pk2(a0.z, a0.z); ffma2(acc[2][0], av, q.x); ffma2(acc[2][1], av, q.y);
            av = pk2(a0.w, a0.w); ffma2(acc[3][0], av, q.x); ffma2(acc[3][1], av, q.y);
            av = pk2(a1.x, a1.x); ffma2(acc[4][0], av, q.x); ffma2(acc[4][1], av, q.y);
            av = pk2(a1.y, a1.y); ffma2(acc[5][0], av, q.x); ffma2(acc[5][1], av, q.y);
            av = pk2(a1.z, a1.z); ffma2(acc[6][0], av, q.x); ffma2(acc[6][1], av, q.y);
            av = pk2(a1.w, a1.w); ffma2(acc[7][0], av, q.x); ffma2(acc[7][1], av, q.y);
        }

        // epilogue with 2-deep x prefetch (L2 hits thanks to the prefetch above)
        float4 xv0 = *reinterpret_cast<const float4*>(x + base0);
        float4 xv1 = *reinterpret_cast<const float4*>(x + base0 + (size_t)HH * WW);

        #pragma unroll
        for (int oi = 0; oi < 8; oi++) {
            const float4 xv = xv0;
            xv0 = xv1;
            if (oi < 6) xv1 = *reinterpret_cast<const float4*>(x + base0 + (size_t)(oi + 2) * HH * WW);
            const float bo = be_[oi];
            float t0, t1, t2, t3;
            upk2(acc[oi][0], t0, t1);
            upk2(acc[oi][1], t2, t3);
            float4 r;
            r.x = xv.x * (1.0f + sigf(t0 + bo));
            r.y = xv.y * (1.0f + sigf(t1 + bo));
            r.z = xv.z * (1.0f + sigf(t2 + bo));
            r.w = xv.w * (1.0f + sigf(t3 + bo));
            *reinterpret_cast<float4*>(out + base0 + (size_t)oi * HH * WW) = r;
        }
    }
}

extern "C" void kernel_launch(void* const* d_in, const int* in_sizes, int n_in,
                              void* d_out, int out_size) {
    const float* x   = (const float*)d_in[0];
    const float* w_h = (const float*)d_in[1];
    const float* b_h = (const float*)d_in[2];
    const float* w_w = (const float*)d_in[3];
    const float* b_w = (const float*)d_in[4];
    const float* w_e = (const float*)d_in[5];
    const float* b_e = (const float*)d_in[6];
    float* out = (float*)d_out;

    const int smem23 = (2 * PC * WW + 8 * PC * 6) * 4;   // 137216
    const int smem4  = (PC * WH + HB * PC * PC) * 4;     // 65536
    cudaFuncSetAttribute(k23,      cudaFuncAttributeMaxDynamicSharedMemorySize, smem23);
    cudaFuncSetAttribute(k4_apply, cudaFuncAttributeMaxDynamicSharedMemorySize, smem4);

    k1_stats<<<NP * PC, 256>>>(x);
    k23<<<64 + NP * 4, 256, smem23>>>(w_h, b_h, w_w, b_w);
    k4_apply<<<NP * 8 * 2, 256, smem4>>>(x, w_e, b_e, out);
}

// round 11
// speedup vs baseline: 1.3068x; 1.0081x over previous
#include <cuda_runtime.h>

// Problem constants
#define NP    64     // B*NUM_PARTS = 16*4
#define PC    32     // channels per part
#define HH    64
#define WW    512
#define HB    8      // h rows per K4 CTA
#define WQ    128    // w quarter width per K4 CTA

typedef unsigned long long u64;

__device__ __forceinline__ u64 pk2(float a, float b) {
    u64 r; asm("mov.b64 %0, {%1,%2};" : "=l"(r) : "f"(a), "f"(b)); return r;
}
__device__ __forceinline__ void upk2(u64 v, float& a, float& b) {
    asm("mov.b64 {%0,%1}, %2;" : "=f"(a), "=f"(b) : "l"(v));
}
__device__ __forceinline__ void ffma2(u64& d, u64 a, u64 b) {
    asm("fma.rn.f32x2 %0, %1, %2, %0;" : "+l"(d) : "l"(a), "l"(b));
}

// branchless sigmoid: 2 MUFU ops, no divergence, ~2^-21 accuracy
__device__ __forceinline__ float sigf(float t) {
    float e = __expf(-fabsf(t));
    float s = __fdividef(1.0f, 1.0f + e);   // sigmoid(|t|)
    return (t >= 0.0f) ? s : 1.0f - s;
}

// Scratch (device globals, allocation-free)
__device__ float g_havg[NP * PC * HH];
__device__ float g_hmax[NP * PC * HH];
__device__ float g_wavg[NP * PC * WW];
__device__ float g_wmax[NP * PC * WW];
__device__ float g_ph[NP * PC * HH];
__device__ float g_pw[NP * PC * WW];

// ---------------------------------------------------------------------------
// K1: per-(n,c) slice stats. Quad-level shfl reduce + smem partials.
// grid 2048, 256 threads
// ---------------------------------------------------------------------------
__global__ __launch_bounds__(256) void k1_stats(const float* __restrict__ x) {
    const int nc  = blockIdx.x;
    const int tid = threadIdx.x;
    const int r2  = tid >> 7;        // 0/1: which row of a 2-row stripe
    const int c4  = tid & 127;       // float4 column 0..127

    const float4* xs = reinterpret_cast<const float4*>(x + (size_t)nc * HH * WW);

    __shared__ float rs[HH][33], rm[HH][33];   // 33: kill final-reduce bank conflict
    __shared__ float csh[WW], cmh[WW];

    float cs0 = 0.f, cs1 = 0.f, cs2 = 0.f, cs3 = 0.f;
    float cm0 = -3.4e38f, cm1 = -3.4e38f, cm2 = -3.4e38f, cm3 = -3.4e38f;
    const int q = c4 >> 2;

    for (int h0 = 0; h0 < HH; h0 += 2) {
        const int h = h0 + r2;
        float4 v = xs[h * 128 + c4];
        cs0 += v.x; cs1 += v.y; cs2 += v.z; cs3 += v.w;
        cm0 = fmaxf(cm0, v.x); cm1 = fmaxf(cm1, v.y);
        cm2 = fmaxf(cm2, v.z); cm3 = fmaxf(cm3, v.w);
        float s = (v.x + v.y) + (v.z + v.w);
        float m = fmaxf(fmaxf(v.x, v.y), fmaxf(v.z, v.w));
        s += __shfl_xor_sync(0xffffffffu, s, 1);
        m  = fmaxf(m, __shfl_xor_sync(0xffffffffu, m, 1));
        s += __shfl_xor_sync(0xffffffffu, s, 2);
        m  = fmaxf(m, __shfl_xor_sync(0xffffffffu, m, 2));
        if ((tid & 3) == 0) { rs[h][q] = s; rm[h][q] = m; }
    }
    __syncthreads();

    if (tid < HH) {
        float s = 0.f, m = -3.4e38f;
        #pragma unroll
        for (int k = 0; k < 32; k++) { s += rs[tid][k]; m = fmaxf(m, rm[tid][k]); }
        g_havg[nc * HH + tid] = s * (1.0f / (float)WW);
        g_hmax[nc * HH + tid] = m;
    }

    if (r2 == 0) {
        csh[c4 * 4 + 0] = cs0; csh[c4 * 4 + 1] = cs1; csh[c4 * 4 + 2] = cs2; csh[c4 * 4 + 3] = cs3;
        cmh[c4 * 4 + 0] = cm0; cmh[c4 * 4 + 1] = cm1; cmh[c4 * 4 + 2] = cm2; cmh[c4 * 4 + 3] = cm3;
    }
    __syncthreads();
    if (r2 == 1) {
        const int w = c4 * 4;
        g_wavg[nc * WW + w + 0] = (cs0 + csh[w + 0]) * (1.0f / (float)HH);
        g_wavg[nc * WW + w + 1] = (cs1 + csh[w + 1]) * (1.0f / (float)HH);
        g_wavg[nc * WW + w + 2] = (cs2 + csh[w + 2]) * (1.0f / (float)HH);
        g_wavg[nc * WW + w + 3] = (cs3 + csh[w + 3]) * (1.0f / (float)HH);
        g_wmax[nc * WW + w + 0] = fmaxf(cm0, cmh[w + 0]);
        g_wmax[nc * WW + w + 1] = fmaxf(cm1, cmh[w + 1]);
        g_wmax[nc * WW + w + 2] = fmaxf(cm2, cmh[w + 2]);
        g_wmax[nc * WW + w + 3] = fmaxf(cm3, cmh[w + 3]);
    }
}

// ---------------------------------------------------------------------------
// K23: merged ph conv (blocks [0,64)) + pw conv (blocks [64,320), o split 4-way)
// 256 threads. dynamic smem: k3-part needs 34304 floats = 137216 B
// ---------------------------------------------------------------------------
__global__ __launch_bounds__(256) void k23(const float* __restrict__ w_h,
                                           const float* __restrict__ b_h,
                                           const float* __restrict__ w_w,
                                           const float* __restrict__ b_w) {
    extern __shared__ float sm[];
    const int bid = blockIdx.x;
    const int tid = threadIdx.x;

    if (bid < 64) {
        // ---------------- ph: conv 3x2 pad(h)=1 + relu + softmax over h ----
        const int n = bid;
        float* ha = sm;                 // [32][64]
        float* hm = sm + PC * HH;       // [32][64]
        float* wh = sm + 2 * PC * HH;   // 6144

        for (int idx = tid; idx < PC * HH; idx += 256) {
            ha[idx] = g_havg[n * PC * HH + idx];
            hm[idx] = g_hmax[n * PC * HH + idx];
        }
        for (int idx = tid; idx < PC * PC * 6; idx += 256) wh[idx] = w_h[idx];
        __syncthreads();

        const int o  = tid >> 3;     // 0..31
        const int j  = tid & 7;      // 8 threads per o, 8 h each
        const int hb = j * 8;

        float acc[8];
        const float bo = b_h[o];
        #pragma unroll
        for (int t = 0; t < 8; t++) acc[t] = bo;

        for (int i = 0; i < PC; i++) {
            const float* wp = &wh[(o * PC + i) * 6];
            const float w00 = wp[0], w01 = wp[1], w10 = wp[2], w11 = wp[3], w20 = wp[4], w21 = wp[5];
            const float* A = ha + i * HH;
            const float* M = hm + i * HH;
            float wA[10], wM[10];
            wA[0] = (hb > 0) ? A[hb - 1] : 0.f;
            wM[0] = (hb > 0) ? M[hb - 1] : 0.f;
            #pragma unroll
            for (int t = 0; t < 8; t++) { wA[t + 1] = A[hb + t]; wM[t + 1] = M[hb + t]; }
            wA[9] = (hb + 8 < HH) ? A[hb + 8] : 0.f;
            wM[9] = (hb + 8 < HH) ? M[hb + 8] : 0.f;
            #pragma unroll
            for (int t = 0; t < 8; t++) {
                acc[t] += wA[t] * w00 + wM[t] * w01
                        + wA[t + 1] * w10 + wM[t + 1] * w11
                        + wA[t + 2] * w20 + wM[t + 2] * w21;
            }
        }

        float lm = -3.4e38f;
        #pragma unroll
        for (int t = 0; t < 8; t++) { acc[t] = fmaxf(acc[t], 0.f); lm = fmaxf(lm, acc[t]); }
        #pragma unroll
        for (int off = 1; off <= 4; off <<= 1) lm = fmaxf(lm, __shfl_xor_sync(0xffffffffu, lm, off));
        float ls = 0.f;
        #pragma unroll
        for (int t = 0; t < 8; t++) { acc[t] = __expf(acc[t] - lm); ls += acc[t]; }
        #pragma unroll
        for (int off = 1; off <= 4; off <<= 1) ls += __shfl_xor_sync(0xffffffffu, ls, off);
        const float inv = 1.0f / ls;
        #pragma unroll
        for (int t = 0; t < 8; t++) g_ph[(n * PC + o) * HH + hb + t] = acc[t] * inv;
    } else {
        // ---------------- pw: conv 2x3 pad(w)=1 + relu + softmax over w ----
        const int b2 = bid - 64;
        const int n  = b2 >> 2;
        const int og = b2 & 3;          // o group of 8

        float* wa = sm;                  // [32][512]
        float* wm = sm + PC * WW;        // [32][512]
        float* ww = sm + 2 * PC * WW;    // 8*32*6 = 1536

        {
            const float4* sa = reinterpret_cast<const float4*>(g_wavg + n * PC * WW);
            const float4* sx = reinterpret_cast<const float4*>(g_wmax + n * PC * WW);
            float4* da = reinterpret_cast<float4*>(wa);
            float4* dm = reinterpret_cast<float4*>(wm);
            for (int idx = tid; idx < PC * WW / 4; idx += 256) { da[idx] = sa[idx]; dm[idx] = sx[idx]; }
        }
        {
            const float* src = w_w + og * 8 * PC * 6;
            for (int idx = tid; idx < 8 * PC * 6; idx += 256) ww[idx] = src[idx];
        }
        __syncthreads();

        const int oo = tid >> 5;            // 0..7 within group
        const int o  = og * 8 + oo;
        const int j  = tid & 31;            // one warp per o

        float acc[16];
        const float bo = b_w[o];
        #pragma unroll
        for (int t = 0; t < 16; t++) acc[t] = bo;

        for (int i = 0; i < PC; i++) {
            const float* wp = &ww[(oo * PC + i) * 6];
            const float a0 = wp[0], a1 = wp[1], a2 = wp[2];
            const float m0 = wp[3], m1 = wp[4], m2 = wp[5];
            const float* A = wa + i * WW;
            const float* M = wm + i * WW;
            #pragma unroll
            for (int k = 0; k < 4; k++) {
                const int w0 = j * 4 + k * 128;
                float4 av = *reinterpret_cast<const float4*>(&A[w0]);
                float4 mv = *reinterpret_cast<const float4*>(&M[w0]);
                float am1 = (w0 > 0) ? A[w0 - 1] : 0.f;
                float mm1 = (w0 > 0) ? M[w0 - 1] : 0.f;
                float ap4 = (w0 + 4 < WW) ? A[w0 + 4] : 0.f;
                float mp4 = (w0 + 4 < WW) ? M[w0 + 4] : 0.f;
                acc[k*4+0] += am1 * a0 + av.x * a1 + av.y * a2 + mm1 * m0 + mv.x * m1 + mv.y * m2;
                acc[k*4+1] += av.x * a0 + av.y * a1 + av.z * a2 + mv.x * m0 + mv.y * m1 + mv.z * m2;
                acc[k*4+2] += av.y * a0 + av.z * a1 + av.w * a2 + mv.y * m0 + mv.z * m1 + mv.w * m2;
                acc[k*4+3] += av.z * a0 + av.w * a1 + ap4 * a2 + mv.z * m0 + mv.w * m1 + mp4 * m2;
            }
        }

        float lm = -3.4e38f;
        #pragma unroll
        for (int t = 0; t < 16; t++) { acc[t] = fmaxf(acc[t], 0.f); lm = fmaxf(lm, acc[t]); }
        #pragma unroll
        for (int off = 1; off <= 16; off <<= 1) lm = fmaxf(lm, __shfl_xor_sync(0xffffffffu, lm, off));
        float ls = 0.f;
        #pragma unroll
        for (int t = 0; t < 16; t++) { acc[t] = __expf(acc[t] - lm); ls += acc[t]; }
        #pragma unroll
        for (int off = 1; off <= 16; off <<= 1) ls += __shfl_xor_sync(0xffffffffu, ls, off);
        const float inv = 1.0f / ls;

        float* dst = g_pw + (n * PC + o) * WW;
        #pragma unroll
        for (int k = 0; k < 4; k++) {
            const int w0 = j * 4 + k * 128;
            float4 r;
            r.x = acc[k*4+0] * inv; r.y = acc[k*4+1] * inv;
            r.z = acc[k*4+2] * inv; r.w = acc[k*4+3] * inv;
            *reinterpret_cast<float4*>(&dst[w0]) = r;
        }
    }
}

// ---------------------------------------------------------------------------
// K4: apply. One CTA per (n, h-block of 8, w-quarter). H-PAIRED mainloop:
// each c-iter processes 2 h rows with a 4-o tile -> 3 LDS (6 wf) + 8 MOV +
// 16 FFMA2 per iter (same ratios as the proven R10 loop) but acc = 32 regs,
// fitting the 64-reg cap of __launch_bounds__(256,4) -> 4 CTAs/SM,
// 8 warps/SMSP (+33% latency hiding). Biases in smem. L2 x-prefetch kept.
// dyn smem: pw[32][128] (16KB) + At8[8][32][32] (32KB) = 48KB
// ---------------------------------------------------------------------------
__global__ __launch_bounds__(256, 4) void k4_apply(const float* __restrict__ x,
                                                   const float* __restrict__ w_e,
                                                   const float* __restrict__ b_e,
                                                   float* __restrict__ out) {
    extern __shared__ float sm4[];
    float* pws = sm4;             // [32][128]
    float* At8 = sm4 + PC * WQ;   // [8][c][o]
    __shared__ float phs[HB * PC];
    __shared__ float bes[PC];

    const int bid = blockIdx.x;
    const int n   = bid >> 5;
    const int hbb = (bid >> 2) & 7;    // h = hbb*8 + hl
    const int wq  = bid & 3;           // w quarter
    const int tid = threadIdx.x;

    // stage pw quarter tile
    {
        const float4* pwg = reinterpret_cast<const float4*>(g_pw + n * PC * WW) + wq * (WQ / 4);
        float4* pw4 = reinterpret_cast<float4*>(pws);
        for (int idx = tid; idx < PC * WQ / 4; idx += 256) {
            const int c = idx >> 5, col = idx & 31;
            pw4[idx] = pwg[c * (WW / 4) + col];
        }
    }
    {
        const int hl = tid >> 5, c = tid & 31;   // 256 = 8*32 exactly
        phs[tid] = g_ph[(n * PC + c) * HH + hbb * HB + hl];
    }
    if (tid < PC) bes[tid] = b_e[tid];
    __syncthreads();

    for (int idx = tid; idx < HB * PC * PC; idx += 256) {
        const int hl = idx >> 10;
        const int c  = (idx >> 5) & 31;
        const int o  = idx & 31;
        At8[idx] = w_e[o * PC + c] * phs[hl * PC + c];
    }
    __syncthreads();

    const int wid  = tid >> 5;        // 0..7
    const int lane = tid & 31;
    const int o0   = wid * 4;         // 4 contiguous o per warp
    const int wofs = lane * 4;        // contiguous w within quarter

    #pragma unroll 1
    for (int hp = 0; hp < HB / 2; hp++) {
        const int h0 = hbb * HB + 2 * hp;
        const float* At0 = At8 + (2 * hp) * (PC * PC);
        const float* At1 = At0 + (PC * PC);
        const size_t base0 = (((size_t)(n * PC + o0)) * HH + h0) * WW + wq * WQ + wofs;

        // L2 prefetch of both h rows' x tiles; covered by the c-loop below
        #pragma unroll
        for (int oi = 0; oi < 4; oi++) {
            asm volatile("prefetch.global.L2 [%0];" :: "l"(x + base0 + (size_t)oi * HH * WW));
            asm volatile("prefetch.global.L2 [%0];" :: "l"(x + base0 + (size_t)oi * HH * WW + WW));
        }

        u64 acA[4][2], acB[4][2];
        #pragma unroll
        for (int oi = 0; oi < 4; oi++) {
            acA[oi][0] = 0ull; acA[oi][1] = 0ull;
            acB[oi][0] = 0ull; acB[oi][1] = 0ull;
        }

        #pragma unroll 4
        for (int c = 0; c < PC; c++) {
            const float4 a0 = *reinterpret_cast<const float4*>(&At0[c * PC + o0]);
            const float4 b0 = *reinterpret_cast<const float4*>(&At1[c * PC + o0]);
            const ulonglong2 q = *reinterpret_cast<const ulonglong2*>(&pws[c * WQ + wofs]);
            u64 av;
            av = pk2(a0.x, a0.x); ffma2(acA[0][0], av, q.x); ffma2(acA[0][1], av, q.y);
            av = pk2(a0.y, a0.y); ffma2(acA[1][0], av, q.x); ffma2(acA[1][1], av, q.y);
            av = pk2(a0.z, a0.z); ffma2(acA[2][0], av, q.x); ffma2(acA[2][1], av, q.y);
            av = pk2(a0.w, a0.w); ffma2(acA[3][0], av, q.x); ffma2(acA[3][1], av, q.y);
            av = pk2(b0.x, b0.x); ffma2(acB[0][0], av, q.x); ffma2(acB[0][1], av, q.y);
            av = pk2(b0.y, b0.y); ffma2(acB[1][0], av, q.x); ffma2(acB[1][1], av, q.y);
            av = pk2(b0.z, b0.z); ffma2(acB[2][0], av, q.x); ffma2(acB[2][1], av, q.y);
            av = pk2(b0.w, b0.w); ffma2(acB[3][0], av, q.x); ffma2(acB[3][1], av, q.y);
        }

        // epilogue: hl0 then hl1 (reuses temps, keeps reg peak low)
        #pragma unroll
        for (int oi = 0; oi < 4; oi++) {
            const float bo = bes[o0 + oi];
            const size_t ba = base0 + (size_t)oi * HH * WW;
            const float4 xv = *reinterpret_cast<const float4*>(x + ba);
            float t0, t1, t2, t3;
            upk2(acA[oi][0], t0, t1);
            upk2(acA[oi][1], t2, t3);
            float4 r;
            r.x = xv.x * (1.0f + sigf(t0 + bo));
            r.y = xv.y * (1.0f + sigf(t1 + bo));
            r.z = xv.z * (1.0f + sigf(t2 + bo));
            r.w = xv.w * (1.0f + sigf(t3 + bo));
            *reinterpret_cast<float4*>(out + ba) = r;
        }
        #pragma unroll
        for (int oi = 0; oi < 4; oi++) {
            const float bo = bes[o0 + oi];
            const size_t ba = base0 + (size_t)oi * HH * WW + WW;
            const float4 xv = *reinterpret_cast<const float4*>(x + ba);
            float t0, t1, t2, t3;
            upk2(acB[oi][0], t0, t1);
            upk2(acB[oi][1], t2, t3);
            float4 r;
            r.x = xv.x * (1.0f + sigf(t0 + bo));
            r.y = xv.y * (1.0f + sigf(t1 + bo));
            r.z = xv.z * (1.0f + sigf(t2 + bo));
            r.w = xv.w * (1.0f + sigf(t3 + bo));
            *reinterpret_cast<float4*>(out + ba) = r;
        }
    }
}

extern "C" void kernel_launch(void* const* d_in, const int* in_sizes, int n_in,
                              void* d_out, int out_size) {
    const float* x   = (const float*)d_in[0];
    const float* w_h = (const float*)d_in[1];
    const float* b_h = (const float*)d_in[2];
    const float* w_w = (const float*)d_in[3];
    const float* b_w = (const float*)d_in[4];
    const float* w_e = (const float*)d_in[5];
    const float* b_e = (const float*)d_in[6];
    float* out = (float*)d_out;

    const int smem23 = (2 * PC * WW + 8 * PC * 6) * 4;   // 137216
    const int smem4  = (PC * WQ + HB * PC * PC) * 4;     // 16384 + 32768 = 49152
    cudaFuncSetAttribute(k23,      cudaFuncAttributeMaxDynamicSharedMemorySize, smem23);
    cudaFuncSetAttribute(k4_apply, cudaFuncAttributeMaxDynamicSharedMemorySize, smem4);

    k1_stats<<<NP * PC, 256>>>(x);
    k23<<<64 + NP * 4, 256, smem23>>>(w_h, b_h, w_w, b_w);
    k4_apply<<<NP * 8 * 4, 256, smem4>>>(x, w_e, b_e, out);
}